// round 2
// baseline (speedup 1.0000x reference)
#include <cuda_runtime.h>
#include <math.h>

#define BB 32
#define TT 512
#define II 1024
#define HH 1024
#define GG 4096   // 4*H

// ---- scratch (static __device__ arrays; no allocation allowed) ----
__device__ float g_xproj[67108864];        // [T][B][4H] = 512*32*4096 (268 MB)
__device__ float g_part[4 * 32 * 32 * 128]; // [ksplit][tile][m=32][n=128] partials (2 MB)
__device__ float g_h[2][BB * HH];           // ping-pong hidden state
__device__ float g_c[BB * HH];              // cell state
__device__ int   g_ctr[32];                 // per-tile arrival counters

__device__ __forceinline__ float sigmoidf_(float x) {
    return 1.0f / (1.0f + __expf(-x));
}

// ---------------------------------------------------------------------------
// init: h <- h0, c <- c0, counters <- 0  (re-run every replay for determinism)
// ---------------------------------------------------------------------------
__global__ void init_kernel(const float* __restrict__ h0, const float* __restrict__ c0) {
    int i = blockIdx.x * blockDim.x + threadIdx.x;
    if (i < BB * HH) { g_h[0][i] = h0[i]; g_c[i] = c0[i]; }
    if (i < 32) g_ctr[i] = 0;
}

// ---------------------------------------------------------------------------
// x_proj = x @ Wi^T + bi + bh
// A row r = (t*32 + b)  <->  x[b][t][:]   (time-major rows for the scan)
// M=16384, N=4096, K=1024.  BM=BN=128, BK=16, 256 thr, 8x8 microtile.
// ---------------------------------------------------------------------------
__global__ __launch_bounds__(256, 2) void xproj_kernel(
    const float* __restrict__ x, const float* __restrict__ Wi,
    const float* __restrict__ bi, const float* __restrict__ bh)
{
    __shared__ float As[16][132];
    __shared__ float Bs[16][132];
    const int bn  = blockIdx.x;   // 0..31  (N tiles)
    const int bm  = blockIdx.y;   // 0..127 (M tiles)
    const int tid = threadIdx.x;
    const int tx  = tid & 15, ty = tid >> 4;

    float acc[8][8];
#pragma unroll
    for (int i = 0; i < 8; i++)
#pragma unroll
        for (int j = 0; j < 8; j++) acc[i][j] = 0.f;

    for (int k0 = 0; k0 < II; k0 += 16) {
#pragma unroll
        for (int u = 0; u < 2; u++) {
            int id  = tid + u * 256;       // 0..511
            int row = id >> 2;             // 0..127
            int k4  = (id & 3) << 2;       // 0,4,8,12
            int grow = bm * 128 + row;
            const float4 va = *(const float4*)(
                x + ((size_t)(grow & 31) * TT + (grow >> 5)) * II + k0 + k4);
            As[k4 + 0][row] = va.x; As[k4 + 1][row] = va.y;
            As[k4 + 2][row] = va.z; As[k4 + 3][row] = va.w;
            const float4 vb = *(const float4*)(
                Wi + (size_t)(bn * 128 + row) * II + k0 + k4);
            Bs[k4 + 0][row] = vb.x; Bs[k4 + 1][row] = vb.y;
            Bs[k4 + 2][row] = vb.z; Bs[k4 + 3][row] = vb.w;
        }
        __syncthreads();
#pragma unroll
        for (int k = 0; k < 16; k++) {
            float av[8], bv[8];
            *(float4*)&av[0] = *(const float4*)&As[k][ty * 8];
            *(float4*)&av[4] = *(const float4*)&As[k][ty * 8 + 4];
            *(float4*)&bv[0] = *(const float4*)&Bs[k][tx * 8];
            *(float4*)&bv[4] = *(const float4*)&Bs[k][tx * 8 + 4];
#pragma unroll
            for (int i = 0; i < 8; i++)
#pragma unroll
                for (int j = 0; j < 8; j++)
                    acc[i][j] = fmaf(av[i], bv[j], acc[i][j]);
        }
        __syncthreads();
    }

    const int colbase = bn * 128 + tx * 8;
    float bias[8];
#pragma unroll
    for (int j = 0; j < 8; j++) bias[j] = bi[colbase + j] + bh[colbase + j];
#pragma unroll
    for (int i = 0; i < 8; i++) {
        int row = bm * 128 + ty * 8 + i;
        float* dst = g_xproj + (size_t)row * GG + colbase;
        float4 v0 = make_float4(acc[i][0] + bias[0], acc[i][1] + bias[1],
                                acc[i][2] + bias[2], acc[i][3] + bias[3]);
        float4 v1 = make_float4(acc[i][4] + bias[4], acc[i][5] + bias[5],
                                acc[i][6] + bias[6], acc[i][7] + bias[7]);
        *(float4*)(dst)     = v0;
        *(float4*)(dst + 4) = v1;
    }
}

// ---------------------------------------------------------------------------
// One recurrence step.  grid = 128 blocks: tile = bx>>2 (32 tiles of 32 h-cols,
// each covering {i,f,g,o} for those cols = 128 gate columns), ks = bx&3 (K split
// of 256).  Last-arriving block per tile fuses the reduction + activations.
// ---------------------------------------------------------------------------
__global__ __launch_bounds__(256) void lstm_step_kernel(
    const float* __restrict__ Wh, float* __restrict__ out, int t)
{
    __shared__ float As[32][36];    // h tile, [k][b]
    __shared__ float Bs[32][132];   // W tile, [k][n]; reused as gates[32][132]
    const int tile = blockIdx.x >> 2;  // 0..31
    const int ks   = blockIdx.x & 3;   // 0..3
    const int tid  = threadIdx.x;
    const int tx   = tid & 31;         // n/4
    const int ty   = tid >> 5;         // m/4 (0..7)
    const float* h_in  = g_h[t & 1];
    float*       h_out = g_h[(t + 1) & 1];

    float acc[4][4];
#pragma unroll
    for (int i = 0; i < 4; i++)
#pragma unroll
        for (int j = 0; j < 4; j++) acc[i][j] = 0.f;

    const int kbase = ks * 256;
    for (int k0 = kbase; k0 < kbase + 256; k0 += 32) {
        {   // A: h_in[b][k0..k0+31] -> As[k][b]
            int b  = tid >> 3;           // 0..31
            int k4 = (tid & 7) << 2;     // 0..28
            const float4 v = *(const float4*)(h_in + b * HH + k0 + k4);
            As[k4 + 0][b] = v.x; As[k4 + 1][b] = v.y;
            As[k4 + 2][b] = v.z; As[k4 + 3][b] = v.w;
        }
#pragma unroll
        for (int u = 0; u < 4; u++) {    // B: 128 gate rows x 32 k
            int id = tid + u * 256;      // 0..1023
            int n  = id >> 3;            // 0..127
            int k4 = (id & 7) << 2;
            int wrow = (n >> 5) * HH + tile * 32 + (n & 31);  // gate*1024 + hcol
            const float4 v = *(const float4*)(Wh + (size_t)wrow * HH + k0 + k4);
            Bs[k4 + 0][n] = v.x; Bs[k4 + 1][n] = v.y;
            Bs[k4 + 2][n] = v.z; Bs[k4 + 3][n] = v.w;
        }
        __syncthreads();
#pragma unroll
        for (int k = 0; k < 32; k++) {
            float4 a  = *(const float4*)&As[k][ty * 4];  // warp-broadcast
            float4 bv = *(const float4*)&Bs[k][tx * 4];  // conflict-free
            float av[4] = {a.x, a.y, a.z, a.w};
            float bw[4] = {bv.x, bv.y, bv.z, bv.w};
#pragma unroll
            for (int i = 0; i < 4; i++)
#pragma unroll
                for (int j = 0; j < 4; j++)
                    acc[i][j] = fmaf(av[i], bw[j], acc[i][j]);
        }
        __syncthreads();
    }

    // publish this block's partial
    float* pbase = g_part + (size_t)(ks * 32 + tile) * 32 * 128;
#pragma unroll
    for (int i = 0; i < 4; i++) {
        int m = ty * 4 + i;
        *(float4*)(pbase + m * 128 + tx * 4) =
            make_float4(acc[i][0], acc[i][1], acc[i][2], acc[i][3]);
    }
    __threadfence();
    __syncthreads();
    __shared__ int s_last;
    if (tid == 0) {
        int old = atomicAdd(&g_ctr[tile], 1);
        s_last = (old == 3) ? 1 : 0;
    }
    __syncthreads();
    if (!s_last) return;
    __threadfence();

    // finisher: sum 4 partials + x_proj[t] into Bs (gates), fixed order -> deterministic
#pragma unroll
    for (int i = 0; i < 4; i++) {
        int m = ty * 4 + i;
#pragma unroll
        for (int j = 0; j < 4; j++) {
            int n = tx * 4 + j;
            float s = 0.f;
#pragma unroll
            for (int p = 0; p < 4; p++)
                s += g_part[(size_t)(p * 32 + tile) * 32 * 128 + m * 128 + n];
            int gcol = (n >> 5) * HH + tile * 32 + (n & 31);
            s += g_xproj[((size_t)t * BB + m) * GG + gcol];
            Bs[m][n] = s;
        }
    }
    __syncthreads();
#pragma unroll
    for (int q = 0; q < 4; q++) {
        int p = tid + q * 256;   // 0..1023 = (b, j)
        int b = p >> 5;
        int j = p & 31;
        float ig = sigmoidf_(Bs[b][j]);
        float fg = sigmoidf_(Bs[b][32 + j]);
        float gg = tanhf(Bs[b][64 + j]);
        float og = sigmoidf_(Bs[b][96 + j]);
        int hc = tile * 32 + j;
        float c_old = g_c[b * HH + hc];
        float c_new = fmaf(fg, c_old, ig * gg);
        float h_new = og * tanhf(c_new);
        g_c[b * HH + hc]   = c_new;
        h_out[b * HH + hc] = h_new;
        out[(size_t)b * TT * HH + (size_t)t * HH + hc] = h_new;  // output[b][t][hc]
    }
    __syncthreads();
    if (tid == 0) g_ctr[tile] = 0;   // reset for next step / next replay
}

// ---------------------------------------------------------------------------
// tail: h_T, c_T appended after output [B,T,H]
// ---------------------------------------------------------------------------
__global__ void finish_kernel(float* __restrict__ out) {
    int i = blockIdx.x * blockDim.x + threadIdx.x;
    if (i < BB * HH) {
        out[(size_t)BB * TT * HH + i]           = g_h[0][i];  // 512 steps -> buf 0
        out[(size_t)BB * TT * HH + BB * HH + i] = g_c[i];
    }
}

extern "C" void kernel_launch(void* const* d_in, const int* in_sizes, int n_in,
                              void* d_out, int out_size) {
    const float* x  = (const float*)d_in[0];
    const float* h0 = (const float*)d_in[1];
    const float* c0 = (const float*)d_in[2];
    const float* Wi = (const float*)d_in[3];
    const float* bi = (const float*)d_in[4];
    const float* Wh = (const float*)d_in[5];
    const float* bh = (const float*)d_in[6];
    float* out = (float*)d_out;

    init_kernel<<<(BB * HH + 255) / 256, 256>>>(h0, c0);
    xproj_kernel<<<dim3(32, 128), 256>>>(x, Wi, bi, bh);
    for (int t = 0; t < TT; t++)
        lstm_step_kernel<<<128, 256>>>(Wh, out, t);
    finish_kernel<<<(BB * HH + 255) / 256, 256>>>(out);
}

// round 5
// speedup vs baseline: 1.2370x; 1.2370x over previous
#include <cuda_runtime.h>
#include <math.h>

#define BB 32
#define TT 512
#define II 1024
#define HH 1024
#define GG 4096   // 4*H

// ---- scratch (static __device__ arrays; no allocation allowed) ----
__device__ float g_xproj[67108864];            // [T][B][4H] = 512*32*4096 (256 MB)
__device__ float g_part[16 * 8 * 32 * 512];    // [ks16][tile8][m32][n512] partials (8 MB)
__device__ float g_h[2][BB * HH];              // ping-pong hidden state
__device__ float g_c[BB * HH];                 // cell state
__device__ unsigned g_bar_cnt;
__device__ volatile unsigned g_bar_gen;

__device__ __forceinline__ float sigmoidf_(float x) {
    return 1.0f / (1.0f + __expf(-x));
}

// packed f32x2 FMA: d(lo,hi) += a(lo,hi) * b(lo,hi)
__device__ __forceinline__ void ffma2(unsigned long long& d,
                                      unsigned long long a,
                                      unsigned long long b) {
    asm("fma.rn.f32x2 %0, %1, %2, %0;" : "+l"(d) : "l"(a), "l"(b));
}

__device__ __forceinline__ float2 u2f2(unsigned long long v) {
    float2 f;
    f.x = __uint_as_float((unsigned)v);
    f.y = __uint_as_float((unsigned)(v >> 32));
    return f;
}

// ---------------------------------------------------------------------------
// init: h <- h0, c <- c0, barrier reset  (re-run every replay for determinism)
// ---------------------------------------------------------------------------
__global__ void init_kernel(const float* __restrict__ h0, const float* __restrict__ c0) {
    int i = blockIdx.x * blockDim.x + threadIdx.x;
    if (i < BB * HH) { g_h[0][i] = h0[i]; g_c[i] = c0[i]; }
    if (i == 0) { g_bar_cnt = 0; g_bar_gen = 0; }
}

// ---------------------------------------------------------------------------
// x_proj = x @ Wi^T + bi + bh   (row r = t*32 + b <-> x[b][t][:])
// M=16384, N=4096, K=1024.  BM=BN=128, BK=16, 256 thr, 8x8 microtile.
// ---------------------------------------------------------------------------
__global__ __launch_bounds__(256, 2) void xproj_kernel(
    const float* __restrict__ x, const float* __restrict__ Wi,
    const float* __restrict__ bi, const float* __restrict__ bh)
{
    __shared__ float As[16][132];
    __shared__ float Bs[16][132];
    const int bn  = blockIdx.x;   // 0..31
    const int bm  = blockIdx.y;   // 0..127
    const int tid = threadIdx.x;
    const int tx  = tid & 15, ty = tid >> 4;

    float acc[8][8];
#pragma unroll
    for (int i = 0; i < 8; i++)
#pragma unroll
        for (int j = 0; j < 8; j++) acc[i][j] = 0.f;

    for (int k0 = 0; k0 < II; k0 += 16) {
#pragma unroll
        for (int u = 0; u < 2; u++) {
            int id  = tid + u * 256;
            int row = id >> 2;
            int k4  = (id & 3) << 2;
            int grow = bm * 128 + row;
            const float4 va = *(const float4*)(
                x + ((size_t)(grow & 31) * TT + (grow >> 5)) * II + k0 + k4);
            As[k4 + 0][row] = va.x; As[k4 + 1][row] = va.y;
            As[k4 + 2][row] = va.z; As[k4 + 3][row] = va.w;
            const float4 vb = *(const float4*)(
                Wi + (size_t)(bn * 128 + row) * II + k0 + k4);
            Bs[k4 + 0][row] = vb.x; Bs[k4 + 1][row] = vb.y;
            Bs[k4 + 2][row] = vb.z; Bs[k4 + 3][row] = vb.w;
        }
        __syncthreads();
#pragma unroll
        for (int k = 0; k < 16; k++) {
            float av[8], bv[8];
            *(float4*)&av[0] = *(const float4*)&As[k][ty * 8];
            *(float4*)&av[4] = *(const float4*)&As[k][ty * 8 + 4];
            *(float4*)&bv[0] = *(const float4*)&Bs[k][tx * 8];
            *(float4*)&bv[4] = *(const float4*)&Bs[k][tx * 8 + 4];
#pragma unroll
            for (int i = 0; i < 8; i++)
#pragma unroll
                for (int j = 0; j < 8; j++)
                    acc[i][j] = fmaf(av[i], bv[j], acc[i][j]);
        }
        __syncthreads();
    }

    const int colbase = bn * 128 + tx * 8;
    float bias[8];
#pragma unroll
    for (int j = 0; j < 8; j++) bias[j] = bi[colbase + j] + bh[colbase + j];
#pragma unroll
    for (int i = 0; i < 8; i++) {
        int row = bm * 128 + ty * 8 + i;
        float* dst = g_xproj + (size_t)row * GG + colbase;
        *(float4*)(dst)     = make_float4(acc[i][0] + bias[0], acc[i][1] + bias[1],
                                          acc[i][2] + bias[2], acc[i][3] + bias[3]);
        *(float4*)(dst + 4) = make_float4(acc[i][4] + bias[4], acc[i][5] + bias[5],
                                          acc[i][6] + bias[6], acc[i][7] + bias[7]);
    }
}

// ---------------------------------------------------------------------------
// Persistent recurrence kernel.
// 128 blocks x 256 thr, all co-resident. Block = (tile = bx>>4, ks = bx&15).
// tile owns hcols [tile*128, +128) across all 4 gates -> 512 gate cols.
// ks owns K slice [ks*64, +64). Wh slice (64k x 512n = 128KB) lives in SMEM
// for the whole kernel. Two grid barriers per step; reduction+activation is
// spread over all 128 blocks (8 hcols x 32 b each), fixed order = deterministic.
// ---------------------------------------------------------------------------
__device__ __forceinline__ void grid_sync(unsigned& gen) {
    __syncthreads();
    if (threadIdx.x == 0) {
        __threadfence();
        unsigned arrived = atomicAdd(&g_bar_cnt, 1u);
        if (arrived == gridDim.x - 1) {
            g_bar_cnt = 0;
            __threadfence();
            g_bar_gen = gen + 1;
        } else {
            while (g_bar_gen <= gen) { }
            __threadfence();
        }
    }
    gen++;
    __syncthreads();
}

__global__ __launch_bounds__(256, 1) void lstm_persist(
    const float* __restrict__ Wh, float* __restrict__ out)
{
    extern __shared__ char smem_raw[];
    float* Wh_s = (float*)smem_raw;                                        // [64][512]
    unsigned long long* h_dup = (unsigned long long*)(smem_raw + 131072);  // [64][32]

    const int bx   = blockIdx.x;
    const int tile = bx >> 4;     // 0..7
    const int ks   = bx & 15;     // 0..15
    const int tid  = threadIdx.x;
    const int tx   = tid & 63;    // n-group
    const int ty   = tid >> 6;    // m-group (0..3)
    const int kbase = ks * 64;

    // ---- one-time: load Wh slice into SMEM (transposed to [k][n]) ----
#pragma unroll 4
    for (int u = 0; u < 32; u++) {
        int idx = tid + u * 256;       // 0..8191 = (n, kq)
        int n   = idx >> 4;            // 0..511
        int kq  = idx & 15;            // 0..15 (float4 along k)
        int g   = n >> 7;
        int hc  = tile * 128 + (n & 127);
        const float4 v = *(const float4*)(Wh + (size_t)(g * HH + hc) * HH + kbase + kq * 4);
        Wh_s[(kq * 4 + 0) * 512 + n] = v.x;
        Wh_s[(kq * 4 + 1) * 512 + n] = v.y;
        Wh_s[(kq * 4 + 2) * 512 + n] = v.z;
        Wh_s[(kq * 4 + 3) * 512 + n] = v.w;
    }

    const int rb = tid >> 3;   // batch (0..31): h-load + reduction role
    const int rh = tid & 7;    // hcol-local / k-group

    unsigned gen = 0;

    for (int t = 0; t < TT; t++) {
        const float* h_in  = g_h[t & 1];
        float*       h_out = g_h[(t + 1) & 1];

        // ---- load h slice into SMEM, duplicated into f32x2 pairs ----
        {
            int koff = rh * 8;
            const float4 v0 = *(const float4*)(h_in + rb * HH + kbase + koff);
            const float4 v1 = *(const float4*)(h_in + rb * HH + kbase + koff + 4);
            float vv[8] = {v0.x, v0.y, v0.z, v0.w, v1.x, v1.y, v1.z, v1.w};
#pragma unroll
            for (int i = 0; i < 8; i++) {
                unsigned u = __float_as_uint(vv[i]);
                h_dup[(koff + i) * 32 + rb] = ((unsigned long long)u << 32) | u;
            }
        }
        __syncthreads();

        // ---- GEMM: acc[8m][8n] via packed f32x2 FMA ----
        unsigned long long acc[8][4];
#pragma unroll
        for (int i = 0; i < 8; i++)
#pragma unroll
            for (int j = 0; j < 4; j++) acc[i][j] = 0ULL;

#pragma unroll 4
        for (int k = 0; k < 64; k++) {
            const unsigned long long* hr = h_dup + (k << 5) + (ty << 3);
            ulonglong2 A0 = *(const ulonglong2*)(hr + 0);
            ulonglong2 A1 = *(const ulonglong2*)(hr + 2);
            ulonglong2 A2 = *(const ulonglong2*)(hr + 4);
            ulonglong2 A3 = *(const ulonglong2*)(hr + 6);
            const float* wr = Wh_s + (k << 9);
            ulonglong2 B0 = *(const ulonglong2*)(wr + (tx << 2));
            ulonglong2 B1 = *(const ulonglong2*)(wr + 256 + (tx << 2));
            unsigned long long av[8] = {A0.x, A0.y, A1.x, A1.y, A2.x, A2.y, A3.x, A3.y};
            unsigned long long bv[4] = {B0.x, B0.y, B1.x, B1.y};
#pragma unroll
            for (int i = 0; i < 8; i++)
#pragma unroll
                for (int j = 0; j < 4; j++)
                    ffma2(acc[i][j], av[i], bv[j]);
        }

        // ---- publish partials: g_part[ks][tile][m][n] ----
        float* pb = g_part + ((size_t)(ks * 8 + tile) * 32) * 512;
#pragma unroll
        for (int i = 0; i < 8; i++) {
            int m = ty * 8 + i;
            float2 c0 = u2f2(acc[i][0]), c1 = u2f2(acc[i][1]);
            float2 c2 = u2f2(acc[i][2]), c3 = u2f2(acc[i][3]);
            *(float4*)(pb + m * 512 + tx * 4)       = make_float4(c0.x, c0.y, c1.x, c1.y);
            *(float4*)(pb + m * 512 + 256 + tx * 4) = make_float4(c2.x, c2.y, c3.x, c3.y);
        }

        grid_sync(gen);

        // ---- parallel reduction + activations (1 (b, hc) item per thread) ----
        {
            int hc    = bx * 8 + rh;          // 0..1023
            int rtile = hc >> 7;
            int nb    = hc & 127;
            float s0 = 0.f, s1 = 0.f, s2 = 0.f, s3 = 0.f;
            const float* gp = g_part + ((size_t)rtile * 32 + rb) * 512 + nb;
#pragma unroll
            for (int kk = 0; kk < 16; kk++) {
                const float* p = gp + (size_t)kk * 8 * 32 * 512;
                s0 += p[0]; s1 += p[128]; s2 += p[256]; s3 += p[384];
            }
            const float* xp = g_xproj + ((size_t)t * BB + rb) * GG + hc;
            s0 += xp[0]; s1 += xp[HH]; s2 += xp[2 * HH]; s3 += xp[3 * HH];

            float ig = sigmoidf_(s0);
            float fg = sigmoidf_(s1);
            float gg = tanhf(s2);
            float og = sigmoidf_(s3);
            float c_old = g_c[rb * HH + hc];
            float c_new = fmaf(fg, c_old, ig * gg);
            float h_new = og * tanhf(c_new);
            g_c[rb * HH + hc]   = c_new;
            h_out[rb * HH + hc] = h_new;
            out[(size_t)rb * TT * HH + (size_t)t * HH + hc] = h_new;
        }

        grid_sync(gen);
    }
}

// ---------------------------------------------------------------------------
// tail: h_T, c_T appended after output [B,T,H]
// ---------------------------------------------------------------------------
__global__ void finish_kernel(float* __restrict__ out) {
    int i = blockIdx.x * blockDim.x + threadIdx.x;
    if (i < BB * HH) {
        out[(size_t)BB * TT * HH + i]           = g_h[0][i];   // 512 steps -> buf 0
        out[(size_t)BB * TT * HH + BB * HH + i] = g_c[i];
    }
}

extern "C" void kernel_launch(void* const* d_in, const int* in_sizes, int n_in,
                              void* d_out, int out_size) {
    const float* x  = (const float*)d_in[0];
    const float* h0 = (const float*)d_in[1];
    const float* c0 = (const float*)d_in[2];
    const float* Wi = (const float*)d_in[3];
    const float* bi = (const float*)d_in[4];
    const float* Wh = (const float*)d_in[5];
    const float* bh = (const float*)d_in[6];
    float* out = (float*)d_out;

    cudaFuncSetAttribute(lstm_persist, cudaFuncAttributeMaxDynamicSharedMemorySize,
                         131072 + 16384);

    init_kernel<<<(BB * HH + 255) / 256, 256>>>(h0, c0);
    xproj_kernel<<<dim3(32, 128), 256>>>(x, Wi, bi, bh);
    lstm_persist<<<128, 256, 131072 + 16384>>>(Wh, out);
    finish_kernel<<<(BB * HH + 255) / 256, 256>>>(out);
}